// round 5
// baseline (speedup 1.0000x reference)
#include <cuda_runtime.h>
#include <cstdint>

#define NTOT 16384
#define BLB  4096
#define BULB 6144
#define DIM  128
#define NC   10
#define LST  12

typedef unsigned long long ull;

__device__ float g_F[NTOT * DIM];   // normalized features
__device__ float g_L[NTOT * LST];   // target distribution (padded to 12)
__device__ float g_cnt[NC];
__device__ float g_inv[NC];

__device__ __forceinline__ ull pk2(float x) {
    ull r; asm("mov.b64 %0,{%1,%1};" : "=l"(r) : "f"(x)); return r;
}
__device__ __forceinline__ void fma2(ull& a, ull b, ull c) {
    asm("fma.rn.f32x2 %0,%1,%2,%0;" : "+l"(a) : "l"(b), "l"(c));
}
__device__ __forceinline__ void unp2(ull a, float& lo, float& hi) {
    unsigned l, h;
    asm("mov.b64 {%0,%1},%2;" : "=r"(l), "=r"(h) : "l"(a));
    lo = __uint_as_float(l); hi = __uint_as_float(h);
}
__device__ __forceinline__ float ex2a(float x) {
    float y; asm("ex2.approx.ftz.f32 %0,%1;" : "=f"(y) : "f"(x)); return y;
}

// ------------------------- prep -------------------------
__global__ void k_zero() { if (threadIdx.x < NC) g_cnt[threadIdx.x] = 0.f; }

__global__ void k_prep_lb(const float* __restrict__ oh) {
    int r = blockIdx.x * blockDim.x + threadIdx.x;
    if (r >= BLB) return;
#pragma unroll
    for (int c = 0; c < NC; c++) {
        float v = oh[r * NC + c];
        g_L[r * LST + c] = v;
        if (v != 0.f) atomicAdd(&g_cnt[c], v);
    }
    g_L[r * LST + 10] = 0.f; g_L[r * LST + 11] = 0.f;
}

__global__ void k_prep_ulb(const float* __restrict__ l1, const float* __restrict__ l2) {
    int r = blockIdx.x * blockDim.x + threadIdx.x;
    if (r >= BULB) return;
    float a[NC], b[NC];
#pragma unroll
    for (int i = 0; i < NC; i++) { a[i] = l1[r*NC+i]; b[i] = l2[r*NC+i]; }
    float m1 = -1e30f, m2 = -1e30f;
#pragma unroll
    for (int i = 0; i < NC; i++) { m1 = fmaxf(m1, a[i]); m2 = fmaxf(m2, b[i]); }
    float s1 = 0.f, s2 = 0.f;
#pragma unroll
    for (int i = 0; i < NC; i++) { s1 += expf(2.f*(a[i]-m1)); s2 += expf(2.f*(b[i]-m2)); }
    bool take1 = (s1 <= s2);            // max(prob1) >= max(prob2)
    float lg[NC];
#pragma unroll
    for (int i = 0; i < NC; i++) lg[i] = take1 ? a[i] : b[i];

    // confidence mask: softmax(lg) >= 0.95
    float m = -1e30f;
#pragma unroll
    for (int i = 0; i < NC; i++) m = fmaxf(m, lg[i]);
    float e[NC], s = 0.f;
#pragma unroll
    for (int i = 0; i < NC; i++) { e[i] = expf(lg[i]-m); s += e[i]; }
#pragma unroll
    for (int i = 0; i < NC; i++) if (e[i] < 0.95f * s) lg[i] = 0.f;

    // class count: first-argmax of masked logits, skip if max == 0
    float mx = lg[0]; int idx = 0;
#pragma unroll
    for (int i = 1; i < NC; i++) if (lg[i] > mx) { mx = lg[i]; idx = i; }
    if (mx != 0.f) atomicAdd(&g_cnt[idx], 2.f);   // counted twice (duplicated rows)

    // prob = softmax(lg / 0.5)
    float mm = -1e30f;
#pragma unroll
    for (int i = 0; i < NC; i++) mm = fmaxf(mm, lg[i]);
    float p[NC], ss = 0.f;
#pragma unroll
    for (int i = 0; i < NC; i++) { p[i] = expf(2.f*(lg[i]-mm)); ss += p[i]; }
    float inv = 1.f / ss;
    int r1 = BLB + r, r2 = BLB + BULB + r;
#pragma unroll
    for (int c = 0; c < NC; c++) {
        float v = p[c] * inv;
        g_L[r1*LST + c] = v; g_L[r2*LST + c] = v;
    }
    g_L[r1*LST+10] = 0.f; g_L[r1*LST+11] = 0.f;
    g_L[r2*LST+10] = 0.f; g_L[r2*LST+11] = 0.f;
}

__global__ void k_fin() {
    float tot = 0.f;
#pragma unroll
    for (int c = 0; c < NC; c++) tot += g_cnt[c];
#pragma unroll
    for (int c = 0; c < NC; c++) {
        float d = (g_cnt[c] == 0.f) ? tot : g_cnt[c];
        g_inv[c] = 1.f / d;
    }
}

__global__ void k_norm(const float* __restrict__ lb, const float* __restrict__ an,
                       const float* __restrict__ po) {
    int w = (blockIdx.x * blockDim.x + threadIdx.x) >> 5;
    int ln = threadIdx.x & 31;
    if (w >= NTOT) return;
    const float* s = (w < BLB) ? lb + (size_t)w * DIM
                   : (w < BLB + BULB) ? an + (size_t)(w - BLB) * DIM
                                      : po + (size_t)(w - BLB - BULB) * DIM;
    float4 v = ((const float4*)s)[ln];
    float q = v.x*v.x + v.y*v.y + v.z*v.z + v.w*v.w;
#pragma unroll
    for (int o = 16; o; o >>= 1) q += __shfl_xor_sync(0xffffffffu, q, o);
    float iv = 1.f / fmaxf(sqrtf(q), 1e-12f);
    ((float4*)(g_F + (size_t)w * DIM))[ln] =
        make_float4(v.x*iv, v.y*iv, v.z*iv, v.w*iv);
}

// ------------------------- main attention -------------------------
// 128 CTAs x 256 thr; per-thread 8q x 8k (split cols {4t..,64+4t..});
// tiles transposed [d][row] in smem; streaming softmax (no max needed: dot in [-1,1]).
__global__ void __launch_bounds__(256, 1) k_attn(float* __restrict__ out) {
    extern __shared__ float sm[];
    float* sQ = sm;
    float* sK = sm + DIM * 128;
    int tid = threadIdx.x, tx = tid & 15, ty = tid >> 4;

    // load Q tile (transposed)
    const float* gq = g_F + (size_t)blockIdx.x * 128 * DIM;
#pragma unroll
    for (int i = 0; i < 16; i++) {
        int c = i * 256 + tid;
        int dch = c >> 7, row = c & 127;
        float4 v = *(const float4*)(gq + (size_t)row * DIM + dch * 4);
        sQ[(dch*4+0)*128 + row] = v.x; sQ[(dch*4+1)*128 + row] = v.y;
        sQ[(dch*4+2)*128 + row] = v.z; sQ[(dch*4+3)*128 + row] = v.w;
    }

    float o[8][NC], den[8];
#pragma unroll
    for (int r = 0; r < 8; r++) {
        den[r] = 0.f;
#pragma unroll
        for (int c = 0; c < NC; c++) o[r][c] = 0.f;
    }

    for (int t = 0; t < NTOT / 128; t++) {
        __syncthreads();
        const float* gk = g_F + (size_t)t * 128 * DIM;
#pragma unroll
        for (int i = 0; i < 16; i++) {
            int c = i * 256 + tid;
            int dch = c >> 7, row = c & 127;
            float4 v = *(const float4*)(gk + (size_t)row * DIM + dch * 4);
            sK[(dch*4+0)*128 + row] = v.x; sK[(dch*4+1)*128 + row] = v.y;
            sK[(dch*4+2)*128 + row] = v.z; sK[(dch*4+3)*128 + row] = v.w;
        }
        __syncthreads();

        ull acc[8][4];
#pragma unroll
        for (int r = 0; r < 8; r++)
#pragma unroll
            for (int p = 0; p < 4; p++) acc[r][p] = 0ull;

#pragma unroll 4
        for (int d = 0; d < DIM; d++) {
            const float* Qd = sQ + d * 128;
            const float* Kd = sK + d * 128;
            float4 qa = *(const float4*)(Qd + ty * 4);
            float4 qb = *(const float4*)(Qd + 64 + ty * 4);
            ulonglong2 kA = *(const ulonglong2*)(Kd + tx * 4);
            ulonglong2 kB = *(const ulonglong2*)(Kd + 64 + tx * 4);
            float qv[8] = {qa.x, qa.y, qa.z, qa.w, qb.x, qb.y, qb.z, qb.w};
#pragma unroll
            for (int r = 0; r < 8; r++) {
                ull q2 = pk2(qv[r]);
                fma2(acc[r][0], q2, kA.x); fma2(acc[r][1], q2, kA.y);
                fma2(acc[r][2], q2, kB.x); fma2(acc[r][3], q2, kB.y);
            }
        }

        // PV: w = exp(2*dot); L rows read from global (L2-resident)
#pragma unroll
        for (int j = 0; j < 8; j++) {
            int col = (j < 4) ? tx * 4 + j : 64 + tx * 4 + (j - 4);
            const float* Lg = g_L + (size_t)(t * 128 + col) * LST;
            float4 A = *(const float4*)Lg;
            float4 B = *(const float4*)(Lg + 4);
            float2 C = *(const float2*)(Lg + 8);
            float Lv[NC] = {A.x, A.y, A.z, A.w, B.x, B.y, B.z, B.w, C.x, C.y};
            int p = j >> 1; int hi = j & 1;
#pragma unroll
            for (int r = 0; r < 8; r++) {
                float lo, hf; unp2(acc[r][p], lo, hf);
                float dt = hi ? hf : lo;
                float w = ex2a(dt * 2.8853900817779268f);   // exp(2*dot)
                den[r] += w;
#pragma unroll
                for (int c = 0; c < NC; c++) o[r][c] = fmaf(w, Lv[c], o[r][c]);
            }
        }
    }

    // cross-tx reduction (reuse smem)
    __syncthreads();
#pragma unroll
    for (int r = 0; r < 8; r++) {
        int row = (r < 4) ? ty * 4 + r : 64 + ty * 4 + (r - 4);
        float* dst = sm + (row * 16 + tx) * 11;
#pragma unroll
        for (int c = 0; c < NC; c++) dst[c] = o[r][c];
        dst[10] = den[r];
    }
    __syncthreads();
    float* red = sm + 128 * 16 * 11;   // 22528
    for (int idx = tid; idx < 128 * 11; idx += 256) {
        int q = idx / 11, c = idx - q * 11;
        float s = 0.f;
#pragma unroll
        for (int i = 0; i < 16; i++) s += sm[(q * 16 + i) * 11 + c];
        red[idx] = s;
    }
    __syncthreads();
    if (tid < 128) {
        float dv = 1.f / red[tid * 11 + 10];
        float* op = out + ((size_t)blockIdx.x * 128 + tid) * NC;
#pragma unroll
        for (int c = 0; c < NC; c++) op[c] = red[tid * 11 + c] * dv * g_inv[c];
    }
}

// ------------------------- launcher -------------------------
extern "C" void kernel_launch(void* const* d_in, const int* in_sizes, int n_in,
                              void* d_out, int out_size) {
    const float* anchor   = (const float*)d_in[0];
    const float* positive = (const float*)d_in[1];
    const float* lb_feat  = (const float*)d_in[2];
    const float* lb_oh    = (const float*)d_in[3];
    const float* logits1  = (const float*)d_in[4];
    const float* logits2  = (const float*)d_in[5];
    float* out = (float*)d_out;

    cudaFuncSetAttribute(k_attn, cudaFuncAttributeMaxDynamicSharedMemorySize, 131072);

    k_zero<<<1, 32>>>();
    k_prep_lb<<<BLB / 256, 256>>>(lb_oh);
    k_prep_ulb<<<BULB / 256, 256>>>(logits1, logits2);
    k_fin<<<1, 1>>>();
    k_norm<<<(NTOT * 32) / 256, 256>>>(lb_feat, anchor, positive);
    k_attn<<<128, 256, 131072>>>(out);
}

// round 7
// speedup vs baseline: 3.1829x; 3.1829x over previous
#include <cuda_runtime.h>
#include <cuda_bf16.h>
#include <cstdint>

#define NTOT 16384
#define BLB  4096
#define BULB 6144
#define DIM  128
#define NC   10
#define LSTB 24      // padded bf16 L row stride (global)
#define TILES 128

typedef unsigned long long ull;

// ---------------- device scratch ----------------
__device__ __align__(256) __nv_bfloat16 g_Fhi[NTOT * DIM];
__device__ __align__(256) __nv_bfloat16 g_Flo[NTOT * DIM];
__device__ __align__(256) __nv_bfloat16 g_Lb[NTOT * LSTB];  // 10 probs, [10]=1.0, rest 0
__device__ float g_cnt[NC];
__device__ float g_inv[NC];

// ---------------- helpers ----------------
__device__ __forceinline__ float ex2a(float x) {
    float y; asm("ex2.approx.ftz.f32 %0,%1;" : "=f"(y) : "f"(x)); return y;
}
__device__ __forceinline__ void cpa16(uint32_t dst, const void* src) {
    asm volatile("cp.async.cg.shared.global [%0], [%1], 16;" :: "r"(dst), "l"(src));
}
#define CPC()  asm volatile("cp.async.commit_group;" ::: "memory")
#define CPW0() asm volatile("cp.async.wait_group 0;" ::: "memory")

__device__ __forceinline__ void ldsm4(uint32_t* r, uint32_t a) {
    asm volatile("ldmatrix.sync.aligned.m8n8.x4.shared.b16 {%0,%1,%2,%3},[%4];"
        : "=r"(r[0]), "=r"(r[1]), "=r"(r[2]), "=r"(r[3]) : "r"(a));
}
__device__ __forceinline__ void ldsm4t(uint32_t* r, uint32_t a) {
    asm volatile("ldmatrix.sync.aligned.m8n8.x4.trans.shared.b16 {%0,%1,%2,%3},[%4];"
        : "=r"(r[0]), "=r"(r[1]), "=r"(r[2]), "=r"(r[3]) : "r"(a));
}
__device__ __forceinline__ void mmabf(float* d, const uint32_t* a, uint32_t b0, uint32_t b1) {
    asm volatile("mma.sync.aligned.m16n8k16.row.col.f32.bf16.bf16.f32 "
        "{%0,%1,%2,%3},{%4,%5,%6,%7},{%8,%9},{%0,%1,%2,%3};"
        : "+f"(d[0]), "+f"(d[1]), "+f"(d[2]), "+f"(d[3])
        : "r"(a[0]), "r"(a[1]), "r"(a[2]), "r"(a[3]), "r"(b0), "r"(b1));
}
__device__ __forceinline__ uint32_t packbf(float lo, float hi) {
    uint32_t r; asm("cvt.rn.bf16x2.f32 %0, %1, %2;" : "=r"(r) : "f"(hi), "f"(lo)); return r;
}

// ---------------- smem layout (byte offsets) ----------------
#define S_QHI   0
#define S_KHI(b) (65536 + (b) * 65536)
#define S_L(b)   (196608 + (b) * 6144)
#define SMEM_REQ (208896 + 1024)

// blocked SW128 layout for a 128x128 bf16 tile (row, 16B-chunk 0..15)
__device__ __forceinline__ uint32_t swoff(int row, int ch) {
    return (uint32_t)(((row >> 3) * 1024) + ((ch >> 3) * 16384)
                      + ((row & 7) * 128) + ((((ch & 7) ^ (row & 7)) << 4)));
}

__device__ __forceinline__ void load_ftile(uint32_t dhi, int rowbase, int tid) {
#pragma unroll
    for (int i = 0; i < 16; i++) {
        int idx = i * 256 + tid;
        int lo = idx >> 11;
        int e = idx & 2047;
        int row = e >> 4, ch = e & 15;
        const __nv_bfloat16* src = (lo ? g_Flo : g_Fhi) + (size_t)(rowbase + row) * DIM + ch * 8;
        cpa16(dhi + (uint32_t)(lo * 32768) + swoff(row, ch), src);
    }
}
__device__ __forceinline__ void load_ltile(uint32_t dst, int rowbase, int tid) {
#pragma unroll
    for (int i = 0; i < 2; i++) {
        int idx = i * 256 + tid;
        if (idx < 384) {
            int row = idx / 3, part = idx - row * 3;
            cpa16(dst + (uint32_t)(row * 48 + part * 16),
                  g_Lb + (size_t)(rowbase + row) * LSTB + part * 8);
        }
    }
}

// ---------------- prep kernels ----------------
__global__ void k_zero() { if (threadIdx.x < NC) g_cnt[threadIdx.x] = 0.f; }

__global__ void k_prep_lb(const float* __restrict__ oh) {
    int r = blockIdx.x * blockDim.x + threadIdx.x;
    if (r >= BLB) return;
#pragma unroll
    for (int c = 0; c < NC; c++) {
        float v = oh[r * NC + c];
        g_Lb[r * LSTB + c] = __float2bfloat16(v);
        if (v != 0.f) atomicAdd(&g_cnt[c], v);
    }
    g_Lb[r * LSTB + 10] = __float2bfloat16(1.0f);
#pragma unroll
    for (int c = 11; c < LSTB; c++) g_Lb[r * LSTB + c] = __float2bfloat16(0.0f);
}

__global__ void k_prep_ulb(const float* __restrict__ l1, const float* __restrict__ l2) {
    int r = blockIdx.x * blockDim.x + threadIdx.x;
    if (r >= BULB) return;
    float a[NC], b[NC];
#pragma unroll
    for (int i = 0; i < NC; i++) { a[i] = l1[r*NC+i]; b[i] = l2[r*NC+i]; }
    float m1 = -1e30f, m2 = -1e30f;
#pragma unroll
    for (int i = 0; i < NC; i++) { m1 = fmaxf(m1, a[i]); m2 = fmaxf(m2, b[i]); }
    float s1 = 0.f, s2 = 0.f;
#pragma unroll
    for (int i = 0; i < NC; i++) { s1 += expf(2.f*(a[i]-m1)); s2 += expf(2.f*(b[i]-m2)); }
    bool take1 = (s1 <= s2);
    float lg[NC];
#pragma unroll
    for (int i = 0; i < NC; i++) lg[i] = take1 ? a[i] : b[i];

    float m = -1e30f;
#pragma unroll
    for (int i = 0; i < NC; i++) m = fmaxf(m, lg[i]);
    float e[NC], s = 0.f;
#pragma unroll
    for (int i = 0; i < NC; i++) { e[i] = expf(lg[i]-m); s += e[i]; }
#pragma unroll
    for (int i = 0; i < NC; i++) if (e[i] < 0.95f * s) lg[i] = 0.f;

    float mx = lg[0]; int idx = 0;
#pragma unroll
    for (int i = 1; i < NC; i++) if (lg[i] > mx) { mx = lg[i]; idx = i; }
    if (mx != 0.f) atomicAdd(&g_cnt[idx], 2.f);

    float mm = -1e30f;
#pragma unroll
    for (int i = 0; i < NC; i++) mm = fmaxf(mm, lg[i]);
    float p[NC], ss = 0.f;
#pragma unroll
    for (int i = 0; i < NC; i++) { p[i] = expf(2.f*(lg[i]-mm)); ss += p[i]; }
    float inv = 1.f / ss;
    int r1 = BLB + r, r2 = BLB + BULB + r;
#pragma unroll
    for (int c = 0; c < NC; c++) {
        __nv_bfloat16 v = __float2bfloat16(p[c] * inv);
        g_Lb[r1*LSTB + c] = v; g_Lb[r2*LSTB + c] = v;
    }
    g_Lb[r1*LSTB + 10] = __float2bfloat16(1.0f);
    g_Lb[r2*LSTB + 10] = __float2bfloat16(1.0f);
#pragma unroll
    for (int c = 11; c < LSTB; c++) {
        g_Lb[r1*LSTB + c] = __float2bfloat16(0.0f);
        g_Lb[r2*LSTB + c] = __float2bfloat16(0.0f);
    }
}

__global__ void k_fin() {
    float tot = 0.f;
#pragma unroll
    for (int c = 0; c < NC; c++) tot += g_cnt[c];
#pragma unroll
    for (int c = 0; c < NC; c++)
        g_inv[c] = 1.f / ((g_cnt[c] == 0.f) ? tot : g_cnt[c]);
}

__global__ void k_norm(const float* __restrict__ lb, const float* __restrict__ an,
                       const float* __restrict__ po) {
    int w = (blockIdx.x * blockDim.x + threadIdx.x) >> 5;
    int ln = threadIdx.x & 31;
    if (w >= NTOT) return;
    const float* s = (w < BLB) ? lb + (size_t)w * DIM
                   : (w < BLB + BULB) ? an + (size_t)(w - BLB) * DIM
                                      : po + (size_t)(w - BLB - BULB) * DIM;
    float4 v = ((const float4*)s)[ln];
    float q = v.x*v.x + v.y*v.y + v.z*v.z + v.w*v.w;
#pragma unroll
    for (int o = 16; o; o >>= 1) q += __shfl_xor_sync(0xffffffffu, q, o);
    float iv = 1.f / fmaxf(sqrtf(q), 1e-12f);
    float f[4] = { v.x*iv, v.y*iv, v.z*iv, v.w*iv };
    __nv_bfloat16 hi[4], lo[4];
#pragma unroll
    for (int i = 0; i < 4; i++) {
        hi[i] = __float2bfloat16(f[i]);
        lo[i] = __float2bfloat16(f[i] - __bfloat162float(hi[i]));
    }
    size_t base = (size_t)w * DIM + ln * 4;
    *(__nv_bfloat162*)(g_Fhi + base)     = __nv_bfloat162(hi[0], hi[1]);
    *(__nv_bfloat162*)(g_Fhi + base + 2) = __nv_bfloat162(hi[2], hi[3]);
    *(__nv_bfloat162*)(g_Flo + base)     = __nv_bfloat162(lo[0], lo[1]);
    *(__nv_bfloat162*)(g_Flo + base + 2) = __nv_bfloat162(lo[2], lo[3]);
}

// ---------------- main attention kernel (mma.sync bf16) ----------------
__global__ void __launch_bounds__(256, 1) k_attn(float* __restrict__ out) {
    extern __shared__ char smraw[];
    uint32_t sb0;
    asm("{\n.reg .u64 t;\ncvta.to.shared.u64 t, %1;\ncvt.u32.u64 %0, t;\n}" : "=r"(sb0) : "l"(smraw));
    uint32_t sb = (sb0 + 1023u) & ~1023u;

    int tid = threadIdx.x, wid = tid >> 5, lane = tid & 31;
    int lr = lane & 7, lg = lane >> 3;
    int hbit = lg >> 1;          // 0: k 0-7 matrices, 1: k 8-15
    int rbit = lg & 1;           // second 8-row group

    // prologue loads: Q, K tile 0, L tile 0
    load_ftile(sb + S_QHI, blockIdx.x * 128, tid);
    load_ftile(sb + S_KHI(0), 0, tid);
    load_ltile(sb + S_L(0), 0, tid);
    CPC(); CPW0();
    __syncthreads();

    // per-lane ldmatrix address components
    int row_a = 16 * wid + rbit * 8 + lr;                       // A rows (Q band)
    uint32_t aR = (uint32_t)(((row_a >> 3) * 1024) + ((row_a & 7) * 128));
    uint32_t ax = (uint32_t)(row_a & 7);
    int r0 = rbit * 8 + lr;                                     // B rows base (p adds 2048*p)
    uint32_t bR = (uint32_t)(((r0 >> 3) * 1024) + ((r0 & 7) * 128));
    uint32_t bx = (uint32_t)(r0 & 7);
    uint32_t lOff = (uint32_t)((hbit * 8 + lr) * 48 + rbit * 16);  // L trans frag

    float O0[4] = {0.f, 0.f, 0.f, 0.f};
    float O1[4] = {0.f, 0.f, 0.f, 0.f};

    for (int t = 0; t < TILES; t++) {
        int b = t & 1;
        if (t + 1 < TILES) {
            load_ftile(sb + S_KHI(b ^ 1), (t + 1) * 128, tid);
            load_ltile(sb + S_L(b ^ 1), (t + 1) * 128, tid);
            CPC();
        }

        uint32_t QH = sb + S_QHI;
        uint32_t KH = sb + S_KHI(b);

        float S[16][4];
#pragma unroll
        for (int n = 0; n < 16; n++)
#pragma unroll
            for (int e = 0; e < 4; e++) S[n][e] = 0.f;

#pragma unroll
        for (int s = 0; s < 8; s++) {
            int ch = 2 * s + hbit;
            uint32_t cA = (uint32_t)(((ch >> 3) * 16384) + ((((uint32_t)(ch & 7) ^ ax) << 4)));
            uint32_t cB = (uint32_t)(((ch >> 3) * 16384) + ((((uint32_t)(ch & 7) ^ bx) << 4)));
            uint32_t ah[4], al[4];
            ldsm4(ah, QH + aR + cA);
            ldsm4(al, QH + 32768 + aR + cA);
#pragma unroll
            for (int p = 0; p < 8; p++) {
                uint32_t bh[4], bl[4];
                uint32_t baddr = KH + bR + (uint32_t)(p * 2048) + cB;
                ldsm4(bh, baddr);
                ldsm4(bl, baddr + 32768);
                mmabf(S[2*p],     ah, bh[0], bh[2]);
                mmabf(S[2*p + 1], ah, bh[1], bh[3]);
                mmabf(S[2*p],     al, bh[0], bh[2]);
                mmabf(S[2*p + 1], al, bh[1], bh[3]);
                mmabf(S[2*p],     ah, bl[0], bl[2]);
                mmabf(S[2*p + 1], ah, bl[1], bl[3]);
            }
        }

        // w = exp(2*dot) = exp2(dot * 2/ln2), pack to bf16 A-fragments
        const float C = 2.8853900817779268f;
        uint32_t aw[16][2];
#pragma unroll
        for (int n = 0; n < 16; n++) {
            float w0 = ex2a(S[n][0] * C), w1 = ex2a(S[n][1] * C);
            float w2 = ex2a(S[n][2] * C), w3 = ex2a(S[n][3] * C);
            aw[n][0] = packbf(w0, w1);
            aw[n][1] = packbf(w2, w3);
        }

        // PV GEMM: O += W_bf16 @ Lpad (col 10 of Lpad is ones -> denominator)
        uint32_t Lb = sb + (uint32_t)S_L(b) + lOff;
#pragma unroll
        for (int s = 0; s < 8; s++) {
            uint32_t bf[4];
            ldsm4t(bf, Lb + (uint32_t)(s * 16 * 48));
            uint32_t A[4] = { aw[2*s][0], aw[2*s][1], aw[2*s + 1][0], aw[2*s + 1][1] };
            mmabf(O0, A, bf[0], bf[2]);
            mmabf(O1, A, bf[1], bf[3]);
        }

        if (t + 1 < TILES) CPW0();
        __syncthreads();
    }

    // ---- epilogue: each lane owns rows (16w + lane/4, +8), col pairs ----
    float d0 = __shfl_sync(0xffffffffu, O1[0], (lane & ~3) | 1);
    float d1 = __shfl_sync(0xffffffffu, O1[2], (lane & ~3) | 1);
    float i0 = 1.f / d0, i1 = 1.f / d1;
    int q = blockIdx.x * 128 + 16 * wid + (lane >> 2);
    int cp = 2 * (lane & 3);
    out[(size_t)q * NC + cp]           = O0[0] * i0 * g_inv[cp];
    out[(size_t)q * NC + cp + 1]       = O0[1] * i0 * g_inv[cp + 1];
    out[(size_t)(q + 8) * NC + cp]     = O0[2] * i1 * g_inv[cp];
    out[(size_t)(q + 8) * NC + cp + 1] = O0[3] * i1 * g_inv[cp + 1];
    if ((lane & 3) == 0) {
        out[(size_t)q * NC + 8]           = O1[0] * i0 * g_inv[8];
        out[(size_t)q * NC + 9]           = O1[1] * i0 * g_inv[9];
        out[(size_t)(q + 8) * NC + 8]     = O1[2] * i1 * g_inv[8];
        out[(size_t)(q + 8) * NC + 9]     = O1[3] * i1 * g_inv[9];
    }
}

// ---------------- launcher ----------------
extern "C" void kernel_launch(void* const* d_in, const int* in_sizes, int n_in,
                              void* d_out, int out_size) {
    const float* anchor   = (const float*)d_in[0];
    const float* positive = (const float*)d_in[1];
    const float* lb_feat  = (const float*)d_in[2];
    const float* lb_oh    = (const float*)d_in[3];
    const float* logits1  = (const float*)d_in[4];
    const float* logits2  = (const float*)d_in[5];
    float* out = (float*)d_out;

    cudaFuncSetAttribute(k_attn, cudaFuncAttributeMaxDynamicSharedMemorySize, SMEM_REQ);

    k_zero<<<1, 32>>>();
    k_prep_lb<<<BLB / 256, 256>>>(lb_oh);
    k_prep_ulb<<<BULB / 256, 256>>>(logits1, logits2);
    k_fin<<<1, 1>>>();
    k_norm<<<(NTOT * 32) / 256, 256>>>(lb_feat, anchor, positive);
    k_attn<<<128, 256, SMEM_REQ>>>(out);
}

// round 8
// speedup vs baseline: 6.9815x; 2.1935x over previous
#include <cuda_runtime.h>
#include <cuda_fp16.h>
#include <cstdint>

#define NTOT 16384
#define BLB  4096
#define BULB 6144
#define DIM  128
#define NC   10
#define LSTB 24      // padded fp16 L row stride (global)
#define TILES 128

// ---------------- device scratch ----------------
__device__ __align__(256) __half g_F[NTOT * DIM];
__device__ __align__(256) __half g_Lh[NTOT * LSTB];  // 10 probs, [10]=1.0, rest 0
__device__ float g_cnt[NC];
__device__ float g_inv[NC];

// ---------------- helpers ----------------
__device__ __forceinline__ float ex2a(float x) {
    float y; asm("ex2.approx.ftz.f32 %0,%1;" : "=f"(y) : "f"(x)); return y;
}
__device__ __forceinline__ void cpa16(uint32_t dst, const void* src) {
    asm volatile("cp.async.cg.shared.global [%0], [%1], 16;" :: "r"(dst), "l"(src));
}
#define CPC()  asm volatile("cp.async.commit_group;" ::: "memory")
#define CPW0() asm volatile("cp.async.wait_group 0;" ::: "memory")

__device__ __forceinline__ void ldsm4(uint32_t* r, uint32_t a) {
    asm volatile("ldmatrix.sync.aligned.m8n8.x4.shared.b16 {%0,%1,%2,%3},[%4];"
        : "=r"(r[0]), "=r"(r[1]), "=r"(r[2]), "=r"(r[3]) : "r"(a));
}
__device__ __forceinline__ void ldsm4t(uint32_t* r, uint32_t a) {
    asm volatile("ldmatrix.sync.aligned.m8n8.x4.trans.shared.b16 {%0,%1,%2,%3},[%4];"
        : "=r"(r[0]), "=r"(r[1]), "=r"(r[2]), "=r"(r[3]) : "r"(a));
}
__device__ __forceinline__ void mmaf16(float* d, const uint32_t* a, uint32_t b0, uint32_t b1) {
    asm volatile("mma.sync.aligned.m16n8k16.row.col.f32.f16.f16.f32 "
        "{%0,%1,%2,%3},{%4,%5,%6,%7},{%8,%9},{%0,%1,%2,%3};"
        : "+f"(d[0]), "+f"(d[1]), "+f"(d[2]), "+f"(d[3])
        : "r"(a[0]), "r"(a[1]), "r"(a[2]), "r"(a[3]), "r"(b0), "r"(b1));
}
__device__ __forceinline__ uint32_t packh(float lo, float hi) {
    uint32_t r; asm("cvt.rn.f16x2.f32 %0, %1, %2;" : "=r"(r) : "f"(hi), "f"(lo)); return r;
}

// ---------------- smem layout (byte offsets from 1024-aligned base) ----------------
#define S_Q     0
#define S_K(b)  (32768 + (b) * 32768)
#define S_L(b)  (98304 + (b) * 6144)
#define SMEM_REQ (110592 + 1024)

// SW128 blocked layout for a 128x128 fp16 tile (row 0..127, 16B-chunk 0..15)
__device__ __forceinline__ uint32_t swoff(int row, int ch) {
    return (uint32_t)(((row >> 3) * 1024) + ((ch >> 3) * 16384)
                      + ((row & 7) * 128) + ((((ch & 7) ^ (row & 7)) << 4)));
}

__device__ __forceinline__ void load_ftile(uint32_t dst, int rowbase, int tid) {
#pragma unroll
    for (int i = 0; i < 8; i++) {
        int idx = i * 256 + tid;
        int row = idx >> 4, ch = idx & 15;
        cpa16(dst + swoff(row, ch), g_F + (size_t)(rowbase + row) * DIM + ch * 8);
    }
}
__device__ __forceinline__ void load_ltile(uint32_t dst, int rowbase, int tid) {
#pragma unroll
    for (int i = 0; i < 2; i++) {
        int idx = i * 256 + tid;
        if (idx < 384) {
            int row = idx / 3, part = idx - row * 3;
            cpa16(dst + (uint32_t)(row * 48 + part * 16),
                  g_Lh + (size_t)(rowbase + row) * LSTB + part * 8);
        }
    }
}

// ---------------- prep kernels ----------------
__global__ void k_zero() { if (threadIdx.x < NC) g_cnt[threadIdx.x] = 0.f; }

__global__ void k_prep_lb(const float* __restrict__ oh) {
    int r = blockIdx.x * blockDim.x + threadIdx.x;
    if (r >= BLB) return;
#pragma unroll
    for (int c = 0; c < NC; c++) {
        float v = oh[r * NC + c];
        g_Lh[r * LSTB + c] = __float2half(v);
        if (v != 0.f) atomicAdd(&g_cnt[c], v);
    }
    g_Lh[r * LSTB + 10] = __float2half(1.0f);
#pragma unroll
    for (int c = 11; c < LSTB; c++) g_Lh[r * LSTB + c] = __float2half(0.0f);
}

__global__ void k_prep_ulb(const float* __restrict__ l1, const float* __restrict__ l2) {
    int r = blockIdx.x * blockDim.x + threadIdx.x;
    if (r >= BULB) return;
    float a[NC], b[NC];
#pragma unroll
    for (int i = 0; i < NC; i++) { a[i] = l1[r*NC+i]; b[i] = l2[r*NC+i]; }
    float m1 = -1e30f, m2 = -1e30f;
#pragma unroll
    for (int i = 0; i < NC; i++) { m1 = fmaxf(m1, a[i]); m2 = fmaxf(m2, b[i]); }
    float s1 = 0.f, s2 = 0.f;
#pragma unroll
    for (int i = 0; i < NC; i++) { s1 += expf(2.f*(a[i]-m1)); s2 += expf(2.f*(b[i]-m2)); }
    bool take1 = (s1 <= s2);
    float lg[NC];
#pragma unroll
    for (int i = 0; i < NC; i++) lg[i] = take1 ? a[i] : b[i];

    float m = -1e30f;
#pragma unroll
    for (int i = 0; i < NC; i++) m = fmaxf(m, lg[i]);
    float e[NC], s = 0.f;
#pragma unroll
    for (int i = 0; i < NC; i++) { e[i] = expf(lg[i]-m); s += e[i]; }
#pragma unroll
    for (int i = 0; i < NC; i++) if (e[i] < 0.95f * s) lg[i] = 0.f;

    float mx = lg[0]; int idx = 0;
#pragma unroll
    for (int i = 1; i < NC; i++) if (lg[i] > mx) { mx = lg[i]; idx = i; }
    if (mx != 0.f) atomicAdd(&g_cnt[idx], 2.f);

    float mm = -1e30f;
#pragma unroll
    for (int i = 0; i < NC; i++) mm = fmaxf(mm, lg[i]);
    float p[NC], ss = 0.f;
#pragma unroll
    for (int i = 0; i < NC; i++) { p[i] = expf(2.f*(lg[i]-mm)); ss += p[i]; }
    float inv = 1.f / ss;
    int r1 = BLB + r, r2 = BLB + BULB + r;
#pragma unroll
    for (int c = 0; c < NC; c++) {
        __half v = __float2half(p[c] * inv);
        g_Lh[r1*LSTB + c] = v; g_Lh[r2*LSTB + c] = v;
    }
    g_Lh[r1*LSTB + 10] = __float2half(1.0f);
    g_Lh[r2*LSTB + 10] = __float2half(1.0f);
#pragma unroll
    for (int c = 11; c < LSTB; c++) {
        g_Lh[r1*LSTB + c] = __float2half(0.0f);
        g_Lh[r2*LSTB + c] = __float2half(0.0f);
    }
}

__global__ void k_fin() {
    float tot = 0.f;
#pragma unroll
    for (int c = 0; c < NC; c++) tot += g_cnt[c];
#pragma unroll
    for (int c = 0; c < NC; c++)
        g_inv[c] = 1.f / ((g_cnt[c] == 0.f) ? tot : g_cnt[c]);
}

__global__ void k_norm(const float* __restrict__ lb, const float* __restrict__ an,
                       const float* __restrict__ po) {
    int w = (blockIdx.x * blockDim.x + threadIdx.x) >> 5;
    int ln = threadIdx.x & 31;
    if (w >= NTOT) return;
    const float* s = (w < BLB) ? lb + (size_t)w * DIM
                   : (w < BLB + BULB) ? an + (size_t)(w - BLB) * DIM
                                      : po + (size_t)(w - BLB - BULB) * DIM;
    float4 v = ((const float4*)s)[ln];
    float q = v.x*v.x + v.y*v.y + v.z*v.z + v.w*v.w;
#pragma unroll
    for (int o = 16; o; o >>= 1) q += __shfl_xor_sync(0xffffffffu, q, o);
    float iv = 1.f / fmaxf(sqrtf(q), 1e-12f);
    __half2 h0 = __floats2half2_rn(v.x * iv, v.y * iv);
    __half2 h1 = __floats2half2_rn(v.z * iv, v.w * iv);
    size_t base = (size_t)w * DIM + ln * 4;
    *(__half2*)(g_F + base)     = h0;
    *(__half2*)(g_F + base + 2) = h1;
}

// ---------------- main attention kernel (fp16 mma.sync) ----------------
__global__ void __launch_bounds__(256, 1) k_attn(float* __restrict__ out) {
    extern __shared__ char smraw[];
    uint32_t sb0;
    asm("{\n.reg .u64 t;\ncvta.to.shared.u64 t, %1;\ncvt.u32.u64 %0, t;\n}" : "=r"(sb0) : "l"(smraw));
    uint32_t sb = (sb0 + 1023u) & ~1023u;

    int tid = threadIdx.x, wid = tid >> 5, lane = tid & 31;
    int lr = lane & 7, lg = lane >> 3;
    int hbit = lg >> 1;          // which k-8-chunk of the k16 step
    int rbit = lg & 1;           // second 8-row group

    // prologue loads: Q, K tile 0, L tile 0
    load_ftile(sb + S_Q, blockIdx.x * 128, tid);
    load_ftile(sb + S_K(0), 0, tid);
    load_ltile(sb + S_L(0), 0, tid);
    CPC(); CPW0();
    __syncthreads();

    // per-lane ldmatrix address components
    int row_a = 16 * wid + rbit * 8 + lr;                       // A rows (Q band)
    uint32_t aR = (uint32_t)(((row_a >> 3) * 1024) + ((row_a & 7) * 128));
    uint32_t ax = (uint32_t)(row_a & 7);
    int r0 = rbit * 8 + lr;                                     // B rows base (p adds 2048*p)
    uint32_t bR = (uint32_t)(((r0 >> 3) * 1024) + ((r0 & 7) * 128));
    uint32_t bx = (uint32_t)(r0 & 7);
    uint32_t lOff = (uint32_t)((hbit * 8 + lr) * 48 + rbit * 16);  // L trans frag

    float O0[4] = {0.f, 0.f, 0.f, 0.f};
    float O1[4] = {0.f, 0.f, 0.f, 0.f};

    for (int t = 0; t < TILES; t++) {
        int b = t & 1;
        if (t + 1 < TILES) {
            load_ftile(sb + S_K(b ^ 1), (t + 1) * 128, tid);
            load_ltile(sb + S_L(b ^ 1), (t + 1) * 128, tid);
            CPC();
        }

        uint32_t QH = sb + S_Q;
        uint32_t KH = sb + S_K(b);

        float S[16][4];
#pragma unroll
        for (int n = 0; n < 16; n++)
#pragma unroll
            for (int e = 0; e < 4; e++) S[n][e] = 0.f;

#pragma unroll
        for (int s = 0; s < 8; s++) {
            int ch = 2 * s + hbit;
            uint32_t cA = (uint32_t)(((ch >> 3) * 16384) + ((((uint32_t)(ch & 7) ^ ax) << 4)));
            uint32_t cB = (uint32_t)(((ch >> 3) * 16384) + ((((uint32_t)(ch & 7) ^ bx) << 4)));
            uint32_t a[4];
            ldsm4(a, QH + aR + cA);
#pragma unroll
            for (int p = 0; p < 8; p++) {
                uint32_t bb[4];
                ldsm4(bb, KH + bR + (uint32_t)(p * 2048) + cB);
                mmaf16(S[2*p],     a, bb[0], bb[2]);
                mmaf16(S[2*p + 1], a, bb[1], bb[3]);
            }
        }

        // w = exp(2*dot) = exp2(dot * 2/ln2), pack to fp16 A-fragments
        const float C = 2.8853900817779268f;
        uint32_t aw[16][2];
#pragma unroll
        for (int n = 0; n < 16; n++) {
            float w0 = ex2a(S[n][0] * C), w1 = ex2a(S[n][1] * C);
            float w2 = ex2a(S[n][2] * C), w3 = ex2a(S[n][3] * C);
            aw[n][0] = packh(w0, w1);
            aw[n][1] = packh(w2, w3);
        }

        // PV GEMM: O += W_f16 @ Lpad (col 10 of Lpad is ones -> denominator)
        uint32_t Lb = sb + (uint32_t)S_L(b) + lOff;
#pragma unroll
        for (int s = 0; s < 8; s++) {
            uint32_t bf[4];
            ldsm4t(bf, Lb + (uint32_t)(s * 16 * 48));
            uint32_t A[4] = { aw[2*s][0], aw[2*s][1], aw[2*s + 1][0], aw[2*s + 1][1] };
            mmaf16(O0, A, bf[0], bf[2]);
            mmaf16(O1, A, bf[1], bf[3]);
        }

        if (t + 1 < TILES) CPW0();
        __syncthreads();
    }

    // ---- epilogue: lane owns rows (16w + lane/4, +8), col pairs 2(lane&3) ----
    float d0 = __shfl_sync(0xffffffffu, O1[0], (lane & ~3) | 1);
    float d1 = __shfl_sync(0xffffffffu, O1[2], (lane & ~3) | 1);
    float i0 = 1.f / d0, i1 = 1.f / d1;
    int q = blockIdx.x * 128 + 16 * wid + (lane >> 2);
    int cp = 2 * (lane & 3);
    out[(size_t)q * NC + cp]           = O0[0] * i0 * g_inv[cp];
    out[(size_t)q * NC + cp + 1]       = O0[1] * i0 * g_inv[cp + 1];
    out[(size_t)(q + 8) * NC + cp]     = O0[2] * i1 * g_inv[cp];
    out[(size_t)(q + 8) * NC + cp + 1] = O0[3] * i1 * g_inv[cp + 1];
    if ((lane & 3) == 0) {
        out[(size_t)q * NC + 8]           = O1[0] * i0 * g_inv[8];
        out[(size_t)q * NC + 9]           = O1[1] * i0 * g_inv[9];
        out[(size_t)(q + 8) * NC + 8]     = O1[2] * i1 * g_inv[8];
        out[(size_t)(q + 8) * NC + 9]     = O1[3] * i1 * g_inv[9];
    }
}

// ---------------- launcher ----------------
extern "C" void kernel_launch(void* const* d_in, const int* in_sizes, int n_in,
                              void* d_out, int out_size) {
    const float* anchor   = (const float*)d_in[0];
    const float* positive = (const float*)d_in[1];
    const float* lb_feat  = (const float*)d_in[2];
    const float* lb_oh    = (const float*)d_in[3];
    const float* logits1  = (const float*)d_in[4];
    const float* logits2  = (const float*)d_in[5];
    float* out = (float*)d_out;

    cudaFuncSetAttribute(k_attn, cudaFuncAttributeMaxDynamicSharedMemorySize, SMEM_REQ);

    k_zero<<<1, 32>>>();
    k_prep_lb<<<BLB / 256, 256>>>(lb_oh);
    k_prep_ulb<<<BULB / 256, 256>>>(logits1, logits2);
    k_fin<<<1, 1>>>();
    k_norm<<<(NTOT * 32) / 256, 256>>>(lb_feat, anchor, positive);
    k_attn<<<128, 256, SMEM_REQ>>>(out);
}

// round 9
// speedup vs baseline: 7.1800x; 1.0284x over previous
#include <cuda_runtime.h>
#include <cuda_fp16.h>
#include <cstdint>

#define NTOT 16384
#define BLB  4096
#define BULB 6144
#define DIM  128
#define NC   10
#define LSTB 24      // padded fp16 L row stride (global)
#define TILES 128

// ---------------- device scratch ----------------
__device__ __align__(256) __half g_F[NTOT * DIM];
__device__ __align__(256) __half g_Lh[NTOT * LSTB];  // 10 probs, [10]=1.0, rest 0
__device__ float g_cnt[NC];

// ---------------- helpers ----------------
__device__ __forceinline__ float ex2a(float x) {
    float y; asm("ex2.approx.ftz.f32 %0,%1;" : "=f"(y) : "f"(x)); return y;
}
__device__ __forceinline__ void cpa16(uint32_t dst, const void* src) {
    asm volatile("cp.async.cg.shared.global [%0], [%1], 16;" :: "r"(dst), "l"(src));
}
#define CPC()  asm volatile("cp.async.commit_group;" ::: "memory")
#define CPW0() asm volatile("cp.async.wait_group 0;" ::: "memory")

__device__ __forceinline__ void ldsm4(uint32_t* r, uint32_t a) {
    asm volatile("ldmatrix.sync.aligned.m8n8.x4.shared.b16 {%0,%1,%2,%3},[%4];"
        : "=r"(r[0]), "=r"(r[1]), "=r"(r[2]), "=r"(r[3]) : "r"(a));
}
__device__ __forceinline__ void ldsm4t(uint32_t* r, uint32_t a) {
    asm volatile("ldmatrix.sync.aligned.m8n8.x4.trans.shared.b16 {%0,%1,%2,%3},[%4];"
        : "=r"(r[0]), "=r"(r[1]), "=r"(r[2]), "=r"(r[3]) : "r"(a));
}
__device__ __forceinline__ void mmaf16(float* d, const uint32_t* a, uint32_t b0, uint32_t b1) {
    asm volatile("mma.sync.aligned.m16n8k16.row.col.f32.f16.f16.f32 "
        "{%0,%1,%2,%3},{%4,%5,%6,%7},{%8,%9},{%0,%1,%2,%3};"
        : "+f"(d[0]), "+f"(d[1]), "+f"(d[2]), "+f"(d[3])
        : "r"(a[0]), "r"(a[1]), "r"(a[2]), "r"(a[3]), "r"(b0), "r"(b1));
}
__device__ __forceinline__ uint32_t packh(float lo, float hi) {
    uint32_t r; asm("cvt.rn.f16x2.f32 %0, %1, %2;" : "=r"(r) : "f"(hi), "f"(lo)); return r;
}

// ---------------- smem layout (byte offsets from 1024-aligned base) ----------------
#define S_Q     0
#define S_K(b)  (32768 + (b) * 32768)
#define S_L(b)  (98304 + (b) * 6144)
#define S_INV   110592
#define SMEM_REQ (110656 + 1024)

// SW128 blocked layout for a 128x128 fp16 tile (row 0..127, 16B-chunk 0..15)
__device__ __forceinline__ uint32_t swoff(int row, int ch) {
    return (uint32_t)(((row >> 3) * 1024) + ((ch >> 3) * 16384)
                      + ((row & 7) * 128) + ((((ch & 7) ^ (row & 7)) << 4)));
}

__device__ __forceinline__ void load_ftile(uint32_t dst, int rowbase, int tid) {
#pragma unroll
    for (int i = 0; i < 8; i++) {
        int idx = i * 256 + tid;
        int row = idx >> 4, ch = idx & 15;
        cpa16(dst + swoff(row, ch), g_F + (size_t)(rowbase + row) * DIM + ch * 8);
    }
}
__device__ __forceinline__ void load_ltile(uint32_t dst, int rowbase, int tid) {
#pragma unroll
    for (int i = 0; i < 2; i++) {
        int idx = i * 256 + tid;
        if (idx < 384) {
            int row = idx / 3, part = idx - row * 3;
            cpa16(dst + (uint32_t)(row * 48 + part * 16),
                  g_Lh + (size_t)(rowbase + row) * LSTB + part * 8);
        }
    }
}

// ---------------- prep kernels ----------------
__global__ void k_zero() { if (threadIdx.x < NC) g_cnt[threadIdx.x] = 0.f; }

__global__ void k_prep_lb(const float* __restrict__ oh) {
    int r = blockIdx.x * blockDim.x + threadIdx.x;
    if (r >= BLB) return;
#pragma unroll
    for (int c = 0; c < NC; c++) {
        float v = oh[r * NC + c];
        g_Lh[r * LSTB + c] = __float2half(v);
        if (v != 0.f) atomicAdd(&g_cnt[c], v);
    }
    g_Lh[r * LSTB + 10] = __float2half(1.0f);
#pragma unroll
    for (int c = 11; c < LSTB; c++) g_Lh[r * LSTB + c] = __float2half(0.0f);
}

__global__ void k_prep_ulb(const float* __restrict__ l1, const float* __restrict__ l2) {
    int r = blockIdx.x * blockDim.x + threadIdx.x;
    if (r >= BULB) return;
    float a[NC], b[NC];
#pragma unroll
    for (int i = 0; i < NC; i++) { a[i] = l1[r*NC+i]; b[i] = l2[r*NC+i]; }
    float m1 = -1e30f, m2 = -1e30f;
#pragma unroll
    for (int i = 0; i < NC; i++) { m1 = fmaxf(m1, a[i]); m2 = fmaxf(m2, b[i]); }
    float s1 = 0.f, s2 = 0.f;
#pragma unroll
    for (int i = 0; i < NC; i++) { s1 += expf(2.f*(a[i]-m1)); s2 += expf(2.f*(b[i]-m2)); }
    bool take1 = (s1 <= s2);
    float lg[NC];
#pragma unroll
    for (int i = 0; i < NC; i++) lg[i] = take1 ? a[i] : b[i];

    float m = -1e30f;
#pragma unroll
    for (int i = 0; i < NC; i++) m = fmaxf(m, lg[i]);
    float e[NC], s = 0.f;
#pragma unroll
    for (int i = 0; i < NC; i++) { e[i] = expf(lg[i]-m); s += e[i]; }
#pragma unroll
    for (int i = 0; i < NC; i++) if (e[i] < 0.95f * s) lg[i] = 0.f;

    float mx = lg[0]; int idx = 0;
#pragma unroll
    for (int i = 1; i < NC; i++) if (lg[i] > mx) { mx = lg[i]; idx = i; }
    if (mx != 0.f) atomicAdd(&g_cnt[idx], 2.f);

    float mm = -1e30f;
#pragma unroll
    for (int i = 0; i < NC; i++) mm = fmaxf(mm, lg[i]);
    float p[NC], ss = 0.f;
#pragma unroll
    for (int i = 0; i < NC; i++) { p[i] = expf(2.f*(lg[i]-mm)); ss += p[i]; }
    float inv = 1.f / ss;
    int r1 = BLB + r, r2 = BLB + BULB + r;
#pragma unroll
    for (int c = 0; c < NC; c++) {
        __half v = __float2half(p[c] * inv);
        g_Lh[r1*LSTB + c] = v; g_Lh[r2*LSTB + c] = v;
    }
    g_Lh[r1*LSTB + 10] = __float2half(1.0f);
    g_Lh[r2*LSTB + 10] = __float2half(1.0f);
#pragma unroll
    for (int c = 11; c < LSTB; c++) {
        g_Lh[r1*LSTB + c] = __float2half(0.0f);
        g_Lh[r2*LSTB + c] = __float2half(0.0f);
    }
}

__global__ void k_norm(const float* __restrict__ lb, const float* __restrict__ an,
                       const float* __restrict__ po) {
    int w = (blockIdx.x * blockDim.x + threadIdx.x) >> 5;
    int ln = threadIdx.x & 31;
    if (w >= NTOT) return;
    const float* s = (w < BLB) ? lb + (size_t)w * DIM
                   : (w < BLB + BULB) ? an + (size_t)(w - BLB) * DIM
                                      : po + (size_t)(w - BLB - BULB) * DIM;
    float4 v = ((const float4*)s)[ln];
    float q = v.x*v.x + v.y*v.y + v.z*v.z + v.w*v.w;
#pragma unroll
    for (int o = 16; o; o >>= 1) q += __shfl_xor_sync(0xffffffffu, q, o);
    float iv = 1.f / fmaxf(sqrtf(q), 1e-12f);
    __half2 h0 = __floats2half2_rn(v.x * iv, v.y * iv);
    __half2 h1 = __floats2half2_rn(v.z * iv, v.w * iv);
    size_t base = (size_t)w * DIM + ln * 4;
    *(__half2*)(g_F + base)     = h0;
    *(__half2*)(g_F + base + 2) = h1;
}

// ---------------- main attention kernel (fp16 mma.sync, n-tile-outer) ----------------
__global__ void __launch_bounds__(256, 1) k_attn(float* __restrict__ out) {
    extern __shared__ char smraw[];
    uint32_t sb0;
    asm("{\n.reg .u64 t;\ncvta.to.shared.u64 t, %1;\ncvt.u32.u64 %0, t;\n}" : "=r"(sb0) : "l"(smraw));
    uint32_t sb = (sb0 + 1023u) & ~1023u;
    float* sInv = (float*)(smraw + (sb - sb0) + S_INV);

    int tid = threadIdx.x, wid = tid >> 5, lane = tid & 31;
    int lr = lane & 7, lg = lane >> 3;
    int hbit = lg >> 1;          // which k8 chunk of the k16 step
    int rbit = lg & 1;           // second 8-row group

    // prologue loads: Q, K tile 0, L tile 0
    load_ftile(sb + S_Q, blockIdx.x * 128, tid);
    load_ftile(sb + S_K(0), 0, tid);
    load_ltile(sb + S_L(0), 0, tid);
    CPC();
    // per-CTA class inverses (replaces k_fin)
    if (tid == 0) {
        float tot = 0.f;
#pragma unroll
        for (int c = 0; c < NC; c++) tot += g_cnt[c];
#pragma unroll
        for (int c = 0; c < NC; c++) {
            float d = g_cnt[c];
            sInv[c] = 1.f / ((d == 0.f) ? tot : d);
        }
    }
    CPW0();
    __syncthreads();

    // per-lane ldmatrix address components
    int row_a = 16 * wid + rbit * 8 + lr;                       // A rows (Q band)
    uint32_t aR = (uint32_t)(((row_a >> 3) * 1024) + ((row_a & 7) * 128));
    uint32_t ax = (uint32_t)(row_a & 7);
    int r0 = rbit * 8 + lr;                                     // B rows base (p adds 2048*p)
    uint32_t bR = (uint32_t)(((r0 >> 3) * 1024) + ((r0 & 7) * 128));
    uint32_t bx = (uint32_t)(r0 & 7);
    uint32_t lOff = (uint32_t)((hbit * 8 + lr) * 48 + rbit * 16);  // L trans frag

    // hoist A fragments (Q is tile-invariant)
    uint32_t A[8][4];
#pragma unroll
    for (int s = 0; s < 8; s++) {
        int ch = 2 * s + hbit;
        uint32_t cA = (uint32_t)(((ch >> 3) * 16384) + ((((uint32_t)(ch & 7) ^ ax) << 4)));
        ldsm4(A[s], sb + S_Q + aR + cA);
    }
    // precompute B column offsets
    uint32_t cB[8];
#pragma unroll
    for (int s = 0; s < 8; s++) {
        int ch = 2 * s + hbit;
        cB[s] = (uint32_t)(((ch >> 3) * 16384) + ((((uint32_t)(ch & 7) ^ bx) << 4)));
    }

    float O0[4] = {0.f, 0.f, 0.f, 0.f};
    float O1[4] = {0.f, 0.f, 0.f, 0.f};
    const float C = 2.8853900817779268f;   // 2/ln2

    for (int t = 0; t < TILES; t++) {
        int b = t & 1;
        if (t + 1 < TILES) {
            load_ftile(sb + S_K(b ^ 1), (t + 1) * 128, tid);
            load_ltile(sb + S_L(b ^ 1), (t + 1) * 128, tid);
            CPC();
        }
        uint32_t KH = sb + S_K(b) + bR;
        uint32_t Lb = sb + (uint32_t)S_L(b) + lOff;

        // n-tile-outer: score 16 keys -> exp -> PV, while next n-tile's QK issues
#pragma unroll
        for (int p = 0; p < 8; p++) {
            float S0[4] = {0.f, 0.f, 0.f, 0.f};
            float S1[4] = {0.f, 0.f, 0.f, 0.f};
            uint32_t kb = KH + (uint32_t)(p * 2048);
#pragma unroll
            for (int s = 0; s < 8; s++) {
                uint32_t bb[4];
                ldsm4(bb, kb + cB[s]);
                mmaf16(S0, A[s], bb[0], bb[2]);
                mmaf16(S1, A[s], bb[1], bb[3]);
            }
            uint32_t W[4];
            W[0] = packh(ex2a(S0[0] * C), ex2a(S0[1] * C));
            W[1] = packh(ex2a(S0[2] * C), ex2a(S0[3] * C));
            W[2] = packh(ex2a(S1[0] * C), ex2a(S1[1] * C));
            W[3] = packh(ex2a(S1[2] * C), ex2a(S1[3] * C));
            uint32_t bf[4];
            ldsm4t(bf, Lb + (uint32_t)(p * 768));
            mmaf16(O0, W, bf[0], bf[2]);
            mmaf16(O1, W, bf[1], bf[3]);
        }

        if (t + 1 < TILES) CPW0();
        __syncthreads();
    }

    // ---- epilogue: lane owns rows (16w + lane/4, +8), col pairs 2(lane&3) ----
    float d0 = __shfl_sync(0xffffffffu, O1[0], (lane & ~3) | 1);
    float d1 = __shfl_sync(0xffffffffu, O1[2], (lane & ~3) | 1);
    float i0 = 1.f / d0, i1 = 1.f / d1;
    int q = blockIdx.x * 128 + 16 * wid + (lane >> 2);
    int cp = 2 * (lane & 3);
    out[(size_t)q * NC + cp]           = O0[0] * i0 * sInv[cp];
    out[(size_t)q * NC + cp + 1]       = O0[1] * i0 * sInv[cp + 1];
    out[(size_t)(q + 8) * NC + cp]     = O0[2] * i1 * sInv[cp];
    out[(size_t)(q + 8) * NC + cp + 1] = O0[3] * i1 * sInv[cp + 1];
    if ((lane & 3) == 0) {
        out[(size_t)q * NC + 8]           = O1[0] * i0 * sInv[8];
        out[(size_t)q * NC + 9]           = O1[1] * i0 * sInv[9];
        out[(size_t)(q + 8) * NC + 8]     = O1[2] * i1 * sInv[8];
        out[(size_t)(q + 8) * NC + 9]     = O1[3] * i1 * sInv[9];
    }
}

// ---------------- launcher ----------------
extern "C" void kernel_launch(void* const* d_in, const int* in_sizes, int n_in,
                              void* d_out, int out_size) {
    const float* anchor   = (const float*)d_in[0];
    const float* positive = (const float*)d_in[1];
    const float* lb_feat  = (const float*)d_in[2];
    const float* lb_oh    = (const float*)d_in[3];
    const float* logits1  = (const float*)d_in[4];
    const float* logits2  = (const float*)d_in[5];
    float* out = (float*)d_out;

    cudaFuncSetAttribute(k_attn, cudaFuncAttributeMaxDynamicSharedMemorySize, SMEM_REQ);

    k_zero<<<1, 32>>>();
    k_prep_lb<<<BLB / 256, 256>>>(lb_oh);
    k_prep_ulb<<<BULB / 256, 256>>>(logits1, logits2);
    k_norm<<<(NTOT * 32) / 256, 256>>>(lb_feat, anchor, positive);
    k_attn<<<128, 256, SMEM_REQ>>>(out);
}

// round 10
// speedup vs baseline: 9.9409x; 1.3845x over previous
#include <cuda_runtime.h>
#include <cuda_fp16.h>
#include <cstdint>

#define NTOT 16384
#define BLB  4096
#define BULB 6144
#define DIM  128
#define NC   10
#define LSTB 24

// ---------------- device scratch ----------------
__device__ __align__(256) __half g_F[NTOT * DIM];
__device__ __align__(256) __half g_Lh[NTOT * LSTB];     // 10 probs, [10]=1, rest 0
__device__ __align__(256) float g_part[128 * 65 * 128 * 12];  // 51 MB partials
__device__ float g_cnt[NC];

// ---------------- helpers ----------------
__device__ __forceinline__ float ex2a(float x) {
    float y; asm("ex2.approx.ftz.f32 %0,%1;" : "=f"(y) : "f"(x)); return y;
}
__device__ __forceinline__ void cpa16(uint32_t dst, const void* src) {
    asm volatile("cp.async.cg.shared.global [%0], [%1], 16;" :: "r"(dst), "l"(src));
}
#define CPC()  asm volatile("cp.async.commit_group;" ::: "memory")
#define CPW0() asm volatile("cp.async.wait_group 0;" ::: "memory")

__device__ __forceinline__ void ldsm4(uint32_t* r, uint32_t a) {
    asm volatile("ldmatrix.sync.aligned.m8n8.x4.shared.b16 {%0,%1,%2,%3},[%4];"
        : "=r"(r[0]), "=r"(r[1]), "=r"(r[2]), "=r"(r[3]) : "r"(a));
}
__device__ __forceinline__ void ldsm4t(uint32_t* r, uint32_t a) {
    asm volatile("ldmatrix.sync.aligned.m8n8.x4.trans.shared.b16 {%0,%1,%2,%3},[%4];"
        : "=r"(r[0]), "=r"(r[1]), "=r"(r[2]), "=r"(r[3]) : "r"(a));
}
__device__ __forceinline__ void mmaf16(float* d, const uint32_t* a, uint32_t b0, uint32_t b1) {
    asm volatile("mma.sync.aligned.m16n8k16.row.col.f32.f16.f16.f32 "
        "{%0,%1,%2,%3},{%4,%5,%6,%7},{%8,%9},{%0,%1,%2,%3};"
        : "+f"(d[0]), "+f"(d[1]), "+f"(d[2]), "+f"(d[3])
        : "r"(a[0]), "r"(a[1]), "r"(a[2]), "r"(a[3]), "r"(b0), "r"(b1));
}
__device__ __forceinline__ uint32_t packh(float lo, float hi) {
    uint32_t r; asm("cvt.rn.f16x2.f32 %0, %1, %2;" : "=r"(r) : "f"(hi), "f"(lo)); return r;
}
__device__ __forceinline__ void sts32(uint32_t a, uint32_t v) {
    asm volatile("st.shared.b32 [%0],%1;" :: "r"(a), "r"(v) : "memory");
}

// ---------------- smem layout (byte offsets from 1024-aligned base) ----------------
#define S_Q     0
#define S_K(b)  (32768 + (b) * 32768)
#define S_W     98304
#define S_L(b)  (131072 + (b) * 6144)
#define SMEM_REQ (143360 + 1024)

// SW128 blocked layout for a 128x128 fp16 tile (row 0..127, 16B-chunk 0..15)
__device__ __forceinline__ uint32_t swoff(int row, int ch) {
    return (uint32_t)(((row >> 3) * 1024) + ((ch >> 3) * 16384)
                      + ((row & 7) * 128) + ((((ch & 7) ^ (row & 7)) << 4)));
}

__device__ __forceinline__ void load_ftile(uint32_t dst, int rowbase, int tid) {
#pragma unroll
    for (int i = 0; i < 8; i++) {
        int idx = i * 256 + tid;
        int row = idx >> 4, ch = idx & 15;
        cpa16(dst + swoff(row, ch), g_F + (size_t)(rowbase + row) * DIM + ch * 8);
    }
}
__device__ __forceinline__ void load_ltile(uint32_t dst, int rowbase, int tid) {
#pragma unroll
    for (int i = 0; i < 2; i++) {
        int idx = i * 256 + tid;
        if (idx < 384) {
            int row = idx / 3, part = idx - row * 3;
            cpa16(dst + (uint32_t)(row * 48 + part * 16),
                  g_Lh + (size_t)(rowbase + row) * LSTB + part * 8);
        }
    }
}

// ---------------- prep kernels ----------------
__global__ void k_zero() { if (threadIdx.x < NC) g_cnt[threadIdx.x] = 0.f; }

__global__ void k_prep_lb(const float* __restrict__ oh) {
    int r = blockIdx.x * blockDim.x + threadIdx.x;
    if (r >= BLB) return;
#pragma unroll
    for (int c = 0; c < NC; c++) {
        float v = oh[r * NC + c];
        g_Lh[r * LSTB + c] = __float2half(v);
        if (v != 0.f) atomicAdd(&g_cnt[c], v);
    }
    g_Lh[r * LSTB + 10] = __float2half(1.0f);
#pragma unroll
    for (int c = 11; c < LSTB; c++) g_Lh[r * LSTB + c] = __float2half(0.0f);
}

__global__ void k_prep_ulb(const float* __restrict__ l1, const float* __restrict__ l2) {
    int r = blockIdx.x * blockDim.x + threadIdx.x;
    if (r >= BULB) return;
    float a[NC], b[NC];
#pragma unroll
    for (int i = 0; i < NC; i++) { a[i] = l1[r*NC+i]; b[i] = l2[r*NC+i]; }
    float m1 = -1e30f, m2 = -1e30f;
#pragma unroll
    for (int i = 0; i < NC; i++) { m1 = fmaxf(m1, a[i]); m2 = fmaxf(m2, b[i]); }
    float s1 = 0.f, s2 = 0.f;
#pragma unroll
    for (int i = 0; i < NC; i++) { s1 += expf(2.f*(a[i]-m1)); s2 += expf(2.f*(b[i]-m2)); }
    bool take1 = (s1 <= s2);
    float lg[NC];
#pragma unroll
    for (int i = 0; i < NC; i++) lg[i] = take1 ? a[i] : b[i];

    float m = -1e30f;
#pragma unroll
    for (int i = 0; i < NC; i++) m = fmaxf(m, lg[i]);
    float e[NC], s = 0.f;
#pragma unroll
    for (int i = 0; i < NC; i++) { e[i] = expf(lg[i]-m); s += e[i]; }
#pragma unroll
    for (int i = 0; i < NC; i++) if (e[i] < 0.95f * s) lg[i] = 0.f;

    float mx = lg[0]; int idx = 0;
#pragma unroll
    for (int i = 1; i < NC; i++) if (lg[i] > mx) { mx = lg[i]; idx = i; }
    if (mx != 0.f) atomicAdd(&g_cnt[idx], 2.f);

    float mm = -1e30f;
#pragma unroll
    for (int i = 0; i < NC; i++) mm = fmaxf(mm, lg[i]);
    float p[NC], ss = 0.f;
#pragma unroll
    for (int i = 0; i < NC; i++) { p[i] = expf(2.f*(lg[i]-mm)); ss += p[i]; }
    float inv = 1.f / ss;
    int r1 = BLB + r, r2 = BLB + BULB + r;
#pragma unroll
    for (int c = 0; c < NC; c++) {
        __half v = __float2half(p[c] * inv);
        g_Lh[r1*LSTB + c] = v; g_Lh[r2*LSTB + c] = v;
    }
    g_Lh[r1*LSTB + 10] = __float2half(1.0f);
    g_Lh[r2*LSTB + 10] = __float2half(1.0f);
#pragma unroll
    for (int c = 11; c < LSTB; c++) {
        g_Lh[r1*LSTB + c] = __float2half(0.0f);
        g_Lh[r2*LSTB + c] = __float2half(0.0f);
    }
}

__global__ void k_norm(const float* __restrict__ lb, const float* __restrict__ an,
                       const float* __restrict__ po) {
    int w = (blockIdx.x * blockDim.x + threadIdx.x) >> 5;
    int ln = threadIdx.x & 31;
    if (w >= NTOT) return;
    const float* s = (w < BLB) ? lb + (size_t)w * DIM
                   : (w < BLB + BULB) ? an + (size_t)(w - BLB) * DIM
                                      : po + (size_t)(w - BLB - BULB) * DIM;
    float4 v = ((const float4*)s)[ln];
    float q = v.x*v.x + v.y*v.y + v.z*v.z + v.w*v.w;
#pragma unroll
    for (int o = 16; o; o >>= 1) q += __shfl_xor_sync(0xffffffffu, q, o);
    float iv = 1.f / fmaxf(sqrtf(q), 1e-12f);
    __half2 h0 = __floats2half2_rn(v.x * iv, v.y * iv);
    __half2 h1 = __floats2half2_rn(v.z * iv, v.w * iv);
    size_t base = (size_t)w * DIM + ln * 4;
    *(__half2*)(g_F + base)     = h0;
    *(__half2*)(g_F + base + 2) = h1;
}

// ---------------- main attention kernel: symmetric tiles ----------------
// CTA c computes tiles (c, (c+d)&127) for d=0..63 (+64 iff c<64).
// Each off-diagonal tile contributes W.L_j locally and W^T.L_c to row-block j
// (written to g_part[j][slot]); local sum goes to g_part[c][64].
__global__ void __launch_bounds__(256, 1) k_attn() {
    extern __shared__ char smraw[];
    uint32_t sb0;
    asm("{\n.reg .u64 t;\ncvta.to.shared.u64 t, %1;\ncvt.u32.u64 %0, t;\n}" : "=r"(sb0) : "l"(smraw));
    uint32_t sb = (sb0 + 1023u) & ~1023u;

    int tid = threadIdx.x, wid = tid >> 5, lane = tid & 31;
    int c = blockIdx.x;
    int lr = lane & 7, lg = lane >> 3;
    int hbit = lg >> 1;
    int rbit = lg & 1;
    int NT = (c < 64) ? 65 : 64;

    // prologue: Q (block c), K tile d=0 (= block c), L tile d=0 (= L_c)
    load_ftile(sb + S_Q, c * 128, tid);
    load_ftile(sb + S_K(0), c * 128, tid);
    load_ltile(sb + S_L(0), c * 128, tid);
    CPC(); CPW0();
    __syncthreads();

    // per-lane ldmatrix address components (QK, local PV) — as validated R8/R9
    int row_a = 16 * wid + rbit * 8 + lr;
    uint32_t aR = (uint32_t)(((row_a >> 3) * 1024) + ((row_a & 7) * 128));
    uint32_t ax = (uint32_t)(row_a & 7);
    int r0 = rbit * 8 + lr;
    uint32_t bR = (uint32_t)(((r0 >> 3) * 1024) + ((r0 & 7) * 128));
    uint32_t bx = (uint32_t)(r0 & 7);
    uint32_t lOff = (uint32_t)((hbit * 8 + lr) * 48 + rbit * 16);

    uint32_t A[8][4];
#pragma unroll
    for (int s = 0; s < 8; s++) {
        int ch = 2 * s + hbit;
        uint32_t cA = (uint32_t)(((ch >> 3) * 16384) + ((((uint32_t)(ch & 7) ^ ax) << 4)));
        ldsm4(A[s], sb + S_Q + aR + cA);
    }
    uint32_t cB[8];
#pragma unroll
    for (int s = 0; s < 8; s++) {
        int ch = 2 * s + hbit;
        cB[s] = (uint32_t)(((ch >> 3) * 16384) + ((((uint32_t)(ch & 7) ^ bx) << 4)));
    }
    // hoist L_c B-fragments (for transposed PV); S_L(0) currently holds L_c
    uint32_t LC[8][4];
#pragma unroll
    for (int s = 0; s < 8; s++) ldsm4t(LC[s], sb + S_L(0) + lOff + (uint32_t)(s * 768));

    // W-store address components: element (r, kc): swoff(r, kc>>3) + (kc&7)*2
    int rW = 16 * wid + (lane >> 2);
    uint32_t wIn = (uint32_t)(4 * (lane & 3));              // kc0&7 = 2(l&3) -> *2 bytes
    // W^T ldsm.trans addresses: qrow = 16s + ((l>>4)<<3) + (l&7), chunk = 2wid + ((l>>3)&1)
    int qbase = ((lane >> 4) << 3) + (lane & 7);
    int chW = 2 * wid + ((lane >> 3) & 1);

    float O0[4] = {0.f, 0.f, 0.f, 0.f};
    float O1[4] = {0.f, 0.f, 0.f, 0.f};
    const float C = 2.8853900817779268f;   // 2/ln2

    for (int d = 0; d < NT; d++) {
        int b = d & 1;
        int j = (c + d) & 127;
        if (d + 1 < NT) {
            int jn = (c + d + 1) & 127;
            load_ftile(sb + S_K(b ^ 1), jn * 128, tid);
            load_ltile(sb + S_L(b ^ 1), jn * 128, tid);
            CPC();
        }
        uint32_t KH = sb + S_K(b) + bR;
        uint32_t Lb = sb + (uint32_t)S_L(b) + lOff;

#pragma unroll
        for (int p = 0; p < 8; p++) {
            float S0[4] = {0.f, 0.f, 0.f, 0.f};
            float S1[4] = {0.f, 0.f, 0.f, 0.f};
            uint32_t kb = KH + (uint32_t)(p * 2048);
#pragma unroll
            for (int s = 0; s < 8; s++) {
                uint32_t bb[4];
                ldsm4(bb, kb + cB[s]);
                mmaf16(S0, A[s], bb[0], bb[2]);
                mmaf16(S1, A[s], bb[1], bb[3]);
            }
            uint32_t W[4];
            W[0] = packh(ex2a(S0[0] * C), ex2a(S0[1] * C));
            W[1] = packh(ex2a(S0[2] * C), ex2a(S0[3] * C));
            W[2] = packh(ex2a(S1[0] * C), ex2a(S1[1] * C));
            W[3] = packh(ex2a(S1[2] * C), ex2a(S1[3] * C));
            // local PV
            uint32_t bf[4];
            ldsm4t(bf, Lb + (uint32_t)(p * 768));
            mmaf16(O0, W, bf[0], bf[2]);
            mmaf16(O1, W, bf[1], bf[3]);
            // store W to smem for the transpose pass
            // (r, kc0), (r+8, kc0), (r, kc0+8), (r+8, kc0+8); kc0 chunk = 2p
            uint32_t w00 = sb + S_W + swoff(rW, 2 * p) + wIn;
            uint32_t w10 = sb + S_W + swoff(rW + 8, 2 * p) + wIn;
            uint32_t w01 = sb + S_W + swoff(rW, 2 * p + 1) + wIn;
            uint32_t w11 = sb + S_W + swoff(rW + 8, 2 * p + 1) + wIn;
            sts32(w00, W[0]); sts32(w10, W[1]); sts32(w01, W[2]); sts32(w11, W[3]);
        }
        __syncthreads();   // W complete

        if (d > 0) {
            // transposed PV: Of[k-rows 16wid..] += W^T @ L_c
            float F0[4] = {0.f, 0.f, 0.f, 0.f};
            float F1[4] = {0.f, 0.f, 0.f, 0.f};
#pragma unroll
            for (int s = 0; s < 8; s++) {
                uint32_t At[4];
                ldsm4t(At, sb + S_W + swoff(16 * s + qbase, chW));
                mmaf16(F0, At, LC[s][0], LC[s][2]);
                mmaf16(F1, At, LC[s][1], LC[s][3]);
            }
            int slot = (d < 64) ? (d - 1) : 63;
            int krow = 16 * wid + (lane >> 2);
            int cp = 2 * (lane & 3);
            float* pb = g_part + (((size_t)j * 65 + slot) * 128 + krow) * 12;
            *(float2*)(pb + cp)          = make_float2(F0[0], F0[1]);
            *(float2*)(pb + 8 * 12 + cp) = make_float2(F0[2], F0[3]);
            if ((lane & 3) < 2) {
                *(float2*)(pb + 8 + cp)          = make_float2(F1[0], F1[1]);
                *(float2*)(pb + 8 * 12 + 8 + cp) = make_float2(F1[2], F1[3]);
            }
        }

        if (d + 1 < NT) CPW0();
        __syncthreads();   // protect W buffer + K/L swap
    }

    // local partial -> slot 64 of row-block c
    {
        int qrow = 16 * wid + (lane >> 2);
        int cp = 2 * (lane & 3);
        float* pb = g_part + (((size_t)c * 65 + 64) * 128 + qrow) * 12;
        *(float2*)(pb + cp)          = make_float2(O0[0], O0[1]);
        *(float2*)(pb + 8 * 12 + cp) = make_float2(O0[2], O0[3]);
        if ((lane & 3) < 2) {
            *(float2*)(pb + 8 + cp)          = make_float2(O1[0], O1[1]);
            *(float2*)(pb + 8 * 12 + 8 + cp) = make_float2(O1[2], O1[3]);
        }
    }
}

// ---------------- reduction kernel ----------------
__global__ void __launch_bounds__(256) k_red(float* __restrict__ out) {
    __shared__ float acc[1536];
    __shared__ float sInv[NC];
    int j = blockIdx.x, tid = threadIdx.x;
    if (tid == 0) {
        float tot = 0.f;
#pragma unroll
        for (int q = 0; q < NC; q++) tot += g_cnt[q];
#pragma unroll
        for (int q = 0; q < NC; q++) {
            float dd = g_cnt[q];
            sInv[q] = 1.f / ((dd == 0.f) ? tot : dd);
        }
    }
    int nfore = (j >= 64) ? 64 : 63;   // slots 0..62 (+63 if j>=64)
    const float* base = g_part + (size_t)j * 65 * 1536;
#pragma unroll
    for (int i = 0; i < 6; i++) {
        int e = i * 256 + tid;
        float s = base[(size_t)64 * 1536 + e];   // local
        int sl = 0;
        for (; sl + 4 <= nfore; sl += 4) {
            s += base[(size_t)sl * 1536 + e] + base[(size_t)(sl+1) * 1536 + e]
               + base[(size_t)(sl+2) * 1536 + e] + base[(size_t)(sl+3) * 1536 + e];
        }
        for (; sl < nfore; sl++) s += base[(size_t)sl * 1536 + e];
        acc[e] = s;
    }
    __syncthreads();
    for (int t = tid; t < 128 * NC; t += 256) {
        int row = t / NC, q = t - row * NC;
        out[((size_t)j * 128 + row) * NC + q] = acc[row * 12 + q] / acc[row * 12 + 10] * sInv[q];
    }
}

// ---------------- launcher ----------------
extern "C" void kernel_launch(void* const* d_in, const int* in_sizes, int n_in,
                              void* d_out, int out_size) {
    const float* anchor   = (const float*)d_in[0];
    const float* positive = (const float*)d_in[1];
    const float* lb_feat  = (const float*)d_in[2];
    const float* lb_oh    = (const float*)d_in[3];
    const float* logits1  = (const float*)d_in[4];
    const float* logits2  = (const float*)d_in[5];
    float* out = (float*)d_out;

    cudaFuncSetAttribute(k_attn, cudaFuncAttributeMaxDynamicSharedMemorySize, SMEM_REQ);

    k_zero<<<1, 32>>>();
    k_prep_lb<<<BLB / 256, 256>>>(lb_oh);
    k_prep_ulb<<<BULB / 256, 256>>>(logits1, logits2);
    k_norm<<<(NTOT * 32) / 256, 256>>>(lb_feat, anchor, positive);
    k_attn<<<128, 256, SMEM_REQ>>>();
    k_red<<<128, 256>>>(out);
}

// round 11
// speedup vs baseline: 10.0251x; 1.0085x over previous
#include <cuda_runtime.h>
#include <cuda_fp16.h>
#include <cstdint>

#define NTOT 16384
#define BLB  4096
#define BULB 6144
#define DIM  128
#define NC   10
#define LSTB 24

// ---------------- device scratch ----------------
__device__ __align__(256) __half g_F[NTOT * DIM];
__device__ __align__(256) __half g_Lh[NTOT * LSTB];     // 10 probs, [10]=1, rest 0
__device__ __align__(256) float g_part[128 * 65 * 128 * 12];  // 51 MB partials
__device__ float g_cnt[NC];

// ---------------- helpers ----------------
__device__ __forceinline__ float ex2a(float x) {
    float y; asm("ex2.approx.ftz.f32 %0,%1;" : "=f"(y) : "f"(x)); return y;
}
__device__ __forceinline__ void cpa16(uint32_t dst, const void* src) {
    asm volatile("cp.async.cg.shared.global [%0], [%1], 16;" :: "r"(dst), "l"(src));
}
#define CPC()  asm volatile("cp.async.commit_group;" ::: "memory")
#define CPW(n) asm volatile("cp.async.wait_group %0;" :: "n"(n) : "memory")

__device__ __forceinline__ void ldsm4(uint32_t* r, uint32_t a) {
    asm volatile("ldmatrix.sync.aligned.m8n8.x4.shared.b16 {%0,%1,%2,%3},[%4];"
        : "=r"(r[0]), "=r"(r[1]), "=r"(r[2]), "=r"(r[3]) : "r"(a));
}
__device__ __forceinline__ void ldsm4t(uint32_t* r, uint32_t a) {
    asm volatile("ldmatrix.sync.aligned.m8n8.x4.trans.shared.b16 {%0,%1,%2,%3},[%4];"
        : "=r"(r[0]), "=r"(r[1]), "=r"(r[2]), "=r"(r[3]) : "r"(a));
}
__device__ __forceinline__ void mmaf16(float* d, const uint32_t* a, uint32_t b0, uint32_t b1) {
    asm volatile("mma.sync.aligned.m16n8k16.row.col.f32.f16.f16.f32 "
        "{%0,%1,%2,%3},{%4,%5,%6,%7},{%8,%9},{%0,%1,%2,%3};"
        : "+f"(d[0]), "+f"(d[1]), "+f"(d[2]), "+f"(d[3])
        : "r"(a[0]), "r"(a[1]), "r"(a[2]), "r"(a[3]), "r"(b0), "r"(b1));
}
__device__ __forceinline__ uint32_t packh(float lo, float hi) {
    uint32_t r; asm("cvt.rn.f16x2.f32 %0, %1, %2;" : "=r"(r) : "f"(hi), "f"(lo)); return r;
}
__device__ __forceinline__ void sts32(uint32_t a, uint32_t v) {
    asm volatile("st.shared.b32 [%0],%1;" :: "r"(a), "r"(v) : "memory");
}

// ---------------- smem layout (byte offsets from 1024-aligned base) ----------------
#define S_Q     0
#define S_K(b)  (32768 + (b) * 32768)      // 3 buffers
#define S_W(b)  (131072 + (b) * 32768)     // 2 buffers
#define S_L(b)  (196608 + (b) * 6144)      // 3 buffers
#define SMEM_REQ (215040 + 1024)

// SW128 blocked layout for a 128x128 fp16 tile (row 0..127, 16B-chunk 0..15)
__device__ __forceinline__ uint32_t swoff(int row, int ch) {
    return (uint32_t)(((row >> 3) * 1024) + ((ch >> 3) * 16384)
                      + ((row & 7) * 128) + ((((ch & 7) ^ (row & 7)) << 4)));
}

__device__ __forceinline__ void load_ftile(uint32_t dst, int rowbase, int tid) {
#pragma unroll
    for (int i = 0; i < 8; i++) {
        int idx = i * 256 + tid;
        int row = idx >> 4, ch = idx & 15;
        cpa16(dst + swoff(row, ch), g_F + (size_t)(rowbase + row) * DIM + ch * 8);
    }
}
__device__ __forceinline__ void load_ltile(uint32_t dst, int rowbase, int tid) {
#pragma unroll
    for (int i = 0; i < 2; i++) {
        int idx = i * 256 + tid;
        if (idx < 384) {
            int row = idx / 3, part = idx - row * 3;
            cpa16(dst + (uint32_t)(row * 48 + part * 16),
                  g_Lh + (size_t)(rowbase + row) * LSTB + part * 8);
        }
    }
}

// ---------------- prep kernels ----------------
__global__ void k_zero() { if (threadIdx.x < NC) g_cnt[threadIdx.x] = 0.f; }

__global__ void k_prep_lb(const float* __restrict__ oh) {
    int r = blockIdx.x * blockDim.x + threadIdx.x;
    if (r >= BLB) return;
#pragma unroll
    for (int c = 0; c < NC; c++) {
        float v = oh[r * NC + c];
        g_Lh[r * LSTB + c] = __float2half(v);
        if (v != 0.f) atomicAdd(&g_cnt[c], v);
    }
    g_Lh[r * LSTB + 10] = __float2half(1.0f);
#pragma unroll
    for (int c = 11; c < LSTB; c++) g_Lh[r * LSTB + c] = __float2half(0.0f);
}

__global__ void k_prep_ulb(const float* __restrict__ l1, const float* __restrict__ l2) {
    int r = blockIdx.x * blockDim.x + threadIdx.x;
    if (r >= BULB) return;
    float a[NC], b[NC];
#pragma unroll
    for (int i = 0; i < NC; i++) { a[i] = l1[r*NC+i]; b[i] = l2[r*NC+i]; }
    float m1 = -1e30f, m2 = -1e30f;
#pragma unroll
    for (int i = 0; i < NC; i++) { m1 = fmaxf(m1, a[i]); m2 = fmaxf(m2, b[i]); }
    float s1 = 0.f, s2 = 0.f;
#pragma unroll
    for (int i = 0; i < NC; i++) { s1 += expf(2.f*(a[i]-m1)); s2 += expf(2.f*(b[i]-m2)); }
    bool take1 = (s1 <= s2);
    float lg[NC];
#pragma unroll
    for (int i = 0; i < NC; i++) lg[i] = take1 ? a[i] : b[i];

    float m = -1e30f;
#pragma unroll
    for (int i = 0; i < NC; i++) m = fmaxf(m, lg[i]);
    float e[NC], s = 0.f;
#pragma unroll
    for (int i = 0; i < NC; i++) { e[i] = expf(lg[i]-m); s += e[i]; }
#pragma unroll
    for (int i = 0; i < NC; i++) if (e[i] < 0.95f * s) lg[i] = 0.f;

    float mx = lg[0]; int idx = 0;
#pragma unroll
    for (int i = 1; i < NC; i++) if (lg[i] > mx) { mx = lg[i]; idx = i; }
    if (mx != 0.f) atomicAdd(&g_cnt[idx], 2.f);

    float mm = -1e30f;
#pragma unroll
    for (int i = 0; i < NC; i++) mm = fmaxf(mm, lg[i]);
    float p[NC], ss = 0.f;
#pragma unroll
    for (int i = 0; i < NC; i++) { p[i] = expf(2.f*(lg[i]-mm)); ss += p[i]; }
    float inv = 1.f / ss;
    int r1 = BLB + r, r2 = BLB + BULB + r;
#pragma unroll
    for (int c = 0; c < NC; c++) {
        __half v = __float2half(p[c] * inv);
        g_Lh[r1*LSTB + c] = v; g_Lh[r2*LSTB + c] = v;
    }
    g_Lh[r1*LSTB + 10] = __float2half(1.0f);
    g_Lh[r2*LSTB + 10] = __float2half(1.0f);
#pragma unroll
    for (int c = 11; c < LSTB; c++) {
        g_Lh[r1*LSTB + c] = __float2half(0.0f);
        g_Lh[r2*LSTB + c] = __float2half(0.0f);
    }
}

__global__ void k_norm(const float* __restrict__ lb, const float* __restrict__ an,
                       const float* __restrict__ po) {
    int w = (blockIdx.x * blockDim.x + threadIdx.x) >> 5;
    int ln = threadIdx.x & 31;
    if (w >= NTOT) return;
    const float* s = (w < BLB) ? lb + (size_t)w * DIM
                   : (w < BLB + BULB) ? an + (size_t)(w - BLB) * DIM
                                      : po + (size_t)(w - BLB - BULB) * DIM;
    float4 v = ((const float4*)s)[ln];
    float q = v.x*v.x + v.y*v.y + v.z*v.z + v.w*v.w;
#pragma unroll
    for (int o = 16; o; o >>= 1) q += __shfl_xor_sync(0xffffffffu, q, o);
    float iv = 1.f / fmaxf(sqrtf(q), 1e-12f);
    __half2 h0 = __floats2half2_rn(v.x * iv, v.y * iv);
    __half2 h1 = __floats2half2_rn(v.z * iv, v.w * iv);
    size_t base = (size_t)w * DIM + ln * 4;
    *(__half2*)(g_F + base)     = h0;
    *(__half2*)(g_F + base + 2) = h1;
}

// ---------------- main attention kernel: symmetric tiles, 1 sync/tile ----------------
// CTA c computes tiles (c, (c+d)&127) for d=0..63 (+64 iff c<64).
// W.L_j accumulates locally; W^T.L_c goes to g_part[j][slot]; local -> g_part[c][64].
__global__ void __launch_bounds__(256, 1) k_attn() {
    extern __shared__ char smraw[];
    uint32_t sb0;
    asm("{\n.reg .u64 t;\ncvta.to.shared.u64 t, %1;\ncvt.u32.u64 %0, t;\n}" : "=r"(sb0) : "l"(smraw));
    uint32_t sb = (sb0 + 1023u) & ~1023u;

    int tid = threadIdx.x, wid = tid >> 5, lane = tid & 31;
    int c = blockIdx.x;
    int lr = lane & 7, lg = lane >> 3;
    int hbit = lg >> 1;
    int rbit = lg & 1;
    int NT = (c < 64) ? 65 : 64;

    // prologue: group0 = {Q, K0, L0}; group1 = {K1, L1}
    load_ftile(sb + S_Q, c * 128, tid);
    load_ftile(sb + S_K(0), c * 128, tid);
    load_ltile(sb + S_L(0), c * 128, tid);
    CPC();
    {
        int j1 = (c + 1) & 127;
        load_ftile(sb + S_K(1), j1 * 128, tid);
        load_ltile(sb + S_L(1), j1 * 128, tid);
        CPC();
    }
    CPW(1);              // group0 (Q, K0, L0) complete
    __syncthreads();

    // per-lane ldmatrix address components
    int row_a = 16 * wid + rbit * 8 + lr;
    uint32_t aR = (uint32_t)(((row_a >> 3) * 1024) + ((row_a & 7) * 128));
    uint32_t ax = (uint32_t)(row_a & 7);
    int r0 = rbit * 8 + lr;
    uint32_t bR = (uint32_t)(((r0 >> 3) * 1024) + ((r0 & 7) * 128));
    uint32_t bx = (uint32_t)(r0 & 7);
    uint32_t lOff = (uint32_t)((hbit * 8 + lr) * 48 + rbit * 16);

    uint32_t A[8][4];
#pragma unroll
    for (int s = 0; s < 8; s++) {
        int ch = 2 * s + hbit;
        uint32_t cA = (uint32_t)(((ch >> 3) * 16384) + ((((uint32_t)(ch & 7) ^ ax) << 4)));
        ldsm4(A[s], sb + S_Q + aR + cA);
    }
    uint32_t cB[8];
#pragma unroll
    for (int s = 0; s < 8; s++) {
        int ch = 2 * s + hbit;
        cB[s] = (uint32_t)(((ch >> 3) * 16384) + ((((uint32_t)(ch & 7) ^ bx) << 4)));
    }
    // hoist L_c B-fragments (for transposed PV); S_L(0) holds L_c
    uint32_t LC[8][4];
#pragma unroll
    for (int s = 0; s < 8; s++) ldsm4t(LC[s], sb + S_L(0) + lOff + (uint32_t)(s * 768));

    // W-store / W^T-load address components
    int rW = 16 * wid + (lane >> 2);
    uint32_t wIn = (uint32_t)(4 * (lane & 3));
    int qbase = ((lane >> 4) << 3) + (lane & 7);
    int chW = 2 * wid + ((lane >> 3) & 1);

    float O0[4] = {0.f, 0.f, 0.f, 0.f};
    float O1[4] = {0.f, 0.f, 0.f, 0.f};
    const float C = 2.8853900817779268f;   // 2/ln2

    for (int d = 0; d < NT; d++) {
        int kb = d % 3;
        int wb = d & 1;
        int j = (c + d) & 127;
        if (d + 2 < NT) {
            int jn = (c + d + 2) & 127;
            load_ftile(sb + S_K((d + 2) % 3), jn * 128, tid);
            load_ltile(sb + S_L((d + 2) % 3), jn * 128, tid);
            CPC();
        }
        CPW(2);          // group d complete (FIFO), d+1/d+2 may fly
        uint32_t KH = sb + S_K(kb) + bR;
        uint32_t Lb = sb + (uint32_t)S_L(kb) + lOff;
        uint32_t WB = sb + (uint32_t)S_W(wb);

#pragma unroll
        for (int p = 0; p < 8; p++) {
            float S0[4] = {0.f, 0.f, 0.f, 0.f};
            float S1[4] = {0.f, 0.f, 0.f, 0.f};
            uint32_t kbad = KH + (uint32_t)(p * 2048);
#pragma unroll
            for (int s = 0; s < 8; s++) {
                uint32_t bb[4];
                ldsm4(bb, kbad + cB[s]);
                mmaf16(S0, A[s], bb[0], bb[2]);
                mmaf16(S1, A[s], bb[1], bb[3]);
            }
            uint32_t W[4];
            W[0] = packh(ex2a(S0[0] * C), ex2a(S0[1] * C));
            W[1] = packh(ex2a(S0[2] * C), ex2a(S0[3] * C));
            W[2] = packh(ex2a(S1[0] * C), ex2a(S1[1] * C));
            W[3] = packh(ex2a(S1[2] * C), ex2a(S1[3] * C));
            // local PV
            uint32_t bf[4];
            ldsm4t(bf, Lb + (uint32_t)(p * 768));
            mmaf16(O0, W, bf[0], bf[2]);
            mmaf16(O1, W, bf[1], bf[3]);
            // store W for the transpose pass
            sts32(WB + swoff(rW, 2 * p) + wIn,     W[0]);
            sts32(WB + swoff(rW + 8, 2 * p) + wIn, W[1]);
            sts32(WB + swoff(rW, 2 * p + 1) + wIn, W[2]);
            sts32(WB + swoff(rW + 8, 2 * p + 1) + wIn, W[3]);
        }

        __syncthreads();   // single barrier: W(d) complete; K(d)/L(d) reads done

        if (d > 0) {
            // transposed PV: k-rows of tile d get W^T @ L_c
            float F0[4] = {0.f, 0.f, 0.f, 0.f};
            float F1[4] = {0.f, 0.f, 0.f, 0.f};
#pragma unroll
            for (int s = 0; s < 8; s++) {
                uint32_t At[4];
                ldsm4t(At, WB + swoff(16 * s + qbase, chW));
                mmaf16(F0, At, LC[s][0], LC[s][2]);
                mmaf16(F1, At, LC[s][1], LC[s][3]);
            }
            int slot = (d < 64) ? (d - 1) : 63;
            int krow = 16 * wid + (lane >> 2);
            int cp = 2 * (lane & 3);
            float* pb = g_part + (((size_t)j * 65 + slot) * 128 + krow) * 12;
            *(float2*)(pb + cp)          = make_float2(F0[0], F0[1]);
            *(float2*)(pb + 8 * 12 + cp) = make_float2(F0[2], F0[3]);
            if ((lane & 3) < 2) {
                *(float2*)(pb + 8 + cp)          = make_float2(F1[0], F1[1]);
                *(float2*)(pb + 8 * 12 + 8 + cp) = make_float2(F1[2], F1[3]);
            }
        }
    }

    // local partial -> slot 64 of row-block c
    {
        int qrow = 16 * wid + (lane >> 2);
        int cp = 2 * (lane & 3);
        float* pb = g_part + (((size_t)c * 65 + 64) * 128 + qrow) * 12;
        *(float2*)(pb + cp)          = make_float2(O0[0], O0[1]);
        *(float2*)(pb + 8 * 12 + cp) = make_float2(O0[2], O0[3]);
        if ((lane & 3) < 2) {
            *(float2*)(pb + 8 + cp)          = make_float2(O1[0], O1[1]);
            *(float2*)(pb + 8 * 12 + 8 + cp) = make_float2(O1[2], O1[3]);
        }
    }
}

// ---------------- reduction kernel ----------------
__global__ void __launch_bounds__(256) k_red(float* __restrict__ out) {
    __shared__ float acc[1536];
    __shared__ float sInv[NC];
    int j = blockIdx.x, tid = threadIdx.x;
    if (tid == 0) {
        float tot = 0.f;
#pragma unroll
        for (int q = 0; q < NC; q++) tot += g_cnt[q];
#pragma unroll
        for (int q = 0; q < NC; q++) {
            float dd = g_cnt[q];
            sInv[q] = 1.f / ((dd == 0.f) ? tot : dd);
        }
    }
    int nfore = (j >= 64) ? 64 : 63;   // slots 0..62 (+63 if j>=64)
    const float* base = g_part + (size_t)j * 65 * 1536;
#pragma unroll
    for (int i = 0; i < 6; i++) {
        int e = i * 256 + tid;
        float s = base[(size_t)64 * 1536 + e];   // local
        int sl = 0;
        for (; sl + 4 <= nfore; sl += 4) {
            s += base[(size_t)sl * 1536 + e] + base[(size_t)(sl+1) * 1536 + e]
               + base[(size_t)(sl+2) * 1536 + e] + base[(size_t)(sl+3) * 1536 + e];
        }
        for (; sl < nfore; sl++) s += base[(size_t)sl * 1536 + e];
        acc[e] = s;
    }
    __syncthreads();
    for (int t = tid; t < 128 * NC; t += 256) {
        int row = t / NC, q = t - row * NC;
        out[((size_t)j * 128 + row) * NC + q] = acc[row * 12 + q] / acc[row * 12 + 10] * sInv[q];
    }
}

// ---------------- launcher ----------------
extern "C" void kernel_launch(void* const* d_in, const int* in_sizes, int n_in,
                              void* d_out, int out_size) {
    const float* anchor   = (const float*)d_in[0];
    const float* positive = (const float*)d_in[1];
    const float* lb_feat  = (const float*)d_in[2];
    const float* lb_oh    = (const float*)d_in[3];
    const float* logits1  = (const float*)d_in[4];
    const float* logits2  = (const float*)d_in[5];
    float* out = (float*)d_out;

    cudaFuncSetAttribute(k_attn, cudaFuncAttributeMaxDynamicSharedMemorySize, SMEM_REQ);

    k_zero<<<1, 32>>>();
    k_prep_lb<<<BLB / 256, 256>>>(lb_oh);
    k_prep_ulb<<<BULB / 256, 256>>>(logits1, logits2);
    k_norm<<<(NTOT * 32) / 256, 256>>>(lb_feat, anchor, positive);
    k_attn<<<128, 256, SMEM_REQ>>>();
    k_red<<<128, 256>>>(out);
}